// round 1
// baseline (speedup 1.0000x reference)
#include <cuda_runtime.h>
#include <cuda_bf16.h>
#include <cstdint>

// Problem constants (fixed by the reference)
#define N_B   4
#define C_IN  256
#define H_IM  64
#define W_IM  64
#define OC    256
#define K2    9          // 3x3
#define OMC   27         // 2*K2 offsets + K2 mask
#define HW    (H_IM*W_IM)        // 4096
#define NPIX  (N_B*HW)           // 16384
#define KDIM  (C_IN*K2)          // 2304

// Scratch (device globals: allocation-free rule)
__device__ float g_om[(size_t)N_B * OMC * HW];          // offset-conv output  (~1.7MB)
__device__ float g_col[(size_t)KDIM * NPIX];            // im2col [kc][pixel]  (~151MB)
__device__ float g_wt[(size_t)KDIM * OC];               // weights [kc][oc]    (~2.25MB)

// ---------------------------------------------------------------------------
// Kernel A: offset conv  om[n][oc][ho][wo] = bias[oc] + sum_{c,ky,kx} ...
// grid (64 ho, 27 oc, 4 n), block 64 (wo)
// ---------------------------------------------------------------------------
__global__ void offset_conv_kernel(const float* __restrict__ x,
                                   const float* __restrict__ w,
                                   const float* __restrict__ bias)
{
    const int wo = threadIdx.x;
    const int ho = blockIdx.x;
    const int oc = blockIdx.y;
    const int n  = blockIdx.z;

    __shared__ float sw[C_IN * K2];   // 9KB: weights for this oc
    for (int i = threadIdx.x; i < C_IN * K2; i += 64)
        sw[i] = w[(size_t)oc * C_IN * K2 + i];
    __syncthreads();

    float acc = bias[oc];
    const float* xn = x + ((size_t)n * C_IN * HW);

    for (int c = 0; c < C_IN; c++) {
        const float* xc = xn + ((size_t)c << 12);
        const float* wc = sw + c * 9;
        #pragma unroll
        for (int ky = 0; ky < 3; ky++) {
            int hy = ho + ky - 1;
            if ((unsigned)hy < (unsigned)H_IM) {
                const float* row = xc + (hy << 6);
                float xm = (wo >= 1)          ? row[wo - 1] : 0.f;
                float x0 = row[wo];
                float xp = (wo <= W_IM - 2)   ? row[wo + 1] : 0.f;
                acc += xm * wc[ky*3 + 0] + x0 * wc[ky*3 + 1] + xp * wc[ky*3 + 2];
            }
        }
    }
    g_om[((size_t)(n * OMC + oc) << 12) + (ho << 6) + wo] = acc;
}

// ---------------------------------------------------------------------------
// Kernel B: reorder weights  g_wt[(k*256+c)*256 + oc] = dcn_w[oc][c][k]
// grid 2304 (kc), block 256 (oc)
// ---------------------------------------------------------------------------
__global__ void reorder_w_kernel(const float* __restrict__ dw)
{
    int kc = blockIdx.x;          // k*256 + c
    int oc = threadIdx.x;
    int k = kc >> 8;
    int c = kc & 255;
    g_wt[(size_t)kc * OC + oc] = dw[((size_t)oc * C_IN + c) * K2 + k];
}

// ---------------------------------------------------------------------------
// Kernel C: bilinear sampling -> g_col[kc][pixel]
// grid (64 ho, 4 n, 2 c-half), block 256 = 64 wo x 4 c-groups
// ---------------------------------------------------------------------------
__global__ void sample_kernel(const float* __restrict__ x)
{
    const int ho   = blockIdx.x;
    const int n    = blockIdx.y;
    const int half = blockIdx.z;
    const int tid  = threadIdx.x;

    __shared__ float s_w[K2][4][64];
    __shared__ int   s_idx[K2][4][64];

    // Phase 1: per (wo, k) compute the 4 corner weights (mask+validity folded)
    for (int it = tid; it < 64 * K2; it += 256) {
        int k  = it / 64;
        int wo = it % 64;
        int p  = (ho << 6) + wo;
        const float* omn = g_om + (size_t)n * OMC * HW;

        float oy = omn[((size_t)(2*k    ) << 12) + p];
        float ox = omn[((size_t)(2*k + 1) << 12) + p];
        float mv = omn[((size_t)(18 + k ) << 12) + p];
        float m  = 1.0f / (1.0f + expf(-mv));

        float him = (float)(ho + (k / 3) - 1) + oy;
        float wim = (float)(wo + (k % 3) - 1) + ox;

        float y0 = floorf(him), x0 = floorf(wim);
        float lh = him - y0,    lw = wim - x0;
        float hh = 1.0f - lh,   hw = 1.0f - lw;
        float y1 = y0 + 1.0f,   x1 = x0 + 1.0f;

        float vy0 = (y0 >= 0.f && y0 <= 63.f) ? 1.f : 0.f;
        float vy1 = (y1 >= 0.f && y1 <= 63.f) ? 1.f : 0.f;
        float vx0 = (x0 >= 0.f && x0 <= 63.f) ? 1.f : 0.f;
        float vx1 = (x1 >= 0.f && x1 <= 63.f) ? 1.f : 0.f;

        int iy0 = (int)fminf(fmaxf(y0, 0.f), 63.f);
        int iy1 = (int)fminf(fmaxf(y1, 0.f), 63.f);
        int ix0 = (int)fminf(fmaxf(x0, 0.f), 63.f);
        int ix1 = (int)fminf(fmaxf(x1, 0.f), 63.f);

        s_w[k][0][wo] = hh * hw * m * vy0 * vx0;  s_idx[k][0][wo] = iy0 * 64 + ix0;
        s_w[k][1][wo] = hh * lw * m * vy0 * vx1;  s_idx[k][1][wo] = iy0 * 64 + ix1;
        s_w[k][2][wo] = lh * hw * m * vy1 * vx0;  s_idx[k][2][wo] = iy1 * 64 + ix0;
        s_w[k][3][wo] = lh * lw * m * vy1 * vx1;  s_idx[k][3][wo] = iy1 * 64 + ix1;
    }
    __syncthreads();

    // Phase 2: gather + weight + store. 32 channels per thread.
    const int wo = tid & 63;
    const int cq = tid >> 6;           // 0..3
    const size_t pcol = (size_t)n * HW + (ho << 6) + wo;

    // hoist loop-invariant weights/indices to registers
    float wreg[36];
    int   ireg[36];
    #pragma unroll
    for (int k = 0; k < K2; k++)
        #pragma unroll
        for (int j = 0; j < 4; j++) {
            wreg[k*4+j] = s_w[k][j][wo];
            ireg[k*4+j] = s_idx[k][j][wo];
        }

    for (int ci = 0; ci < 32; ci++) {
        int c = half * 128 + ci * 4 + cq;
        const float* xb = x + ((size_t)(n * C_IN + c) << 12);
        #pragma unroll
        for (int k = 0; k < K2; k++) {
            float v = wreg[k*4+0] * xb[ireg[k*4+0]]
                    + wreg[k*4+1] * xb[ireg[k*4+1]]
                    + wreg[k*4+2] * xb[ireg[k*4+2]]
                    + wreg[k*4+3] * xb[ireg[k*4+3]];
            g_col[(size_t)(k * C_IN + c) * NPIX + pcol] = v;
        }
    }
}

// ---------------------------------------------------------------------------
// Kernel D: SGEMM  out[p][oc] = sum_kc g_col[kc][p] * g_wt[kc][oc]
// BM=128 (p), BN=128 (oc), BK=8, 256 threads, 8x8 microtile
// grid (M/128 = 128, N/128 = 2)
// ---------------------------------------------------------------------------
__global__ __launch_bounds__(256, 2)
void gemm_kernel(float* __restrict__ out)
{
    const int tid = threadIdx.x;
    const int tx  = tid & 15;     // 0..15  (oc dir)
    const int ty  = tid >> 4;     // 0..15  (p dir)
    const int bm0 = blockIdx.x * 128;
    const int bn0 = blockIdx.y * 128;

    __shared__ float As[8][128];
    __shared__ float Bs[8][128];

    float acc[8][8];
    #pragma unroll
    for (int i = 0; i < 8; i++)
        #pragma unroll
        for (int j = 0; j < 8; j++) acc[i][j] = 0.f;

    const int lr = tid >> 5;           // 0..7
    const int lc = (tid & 31) * 4;     // 0..124

    for (int k0 = 0; k0 < KDIM; k0 += 8) {
        // load A tile: g_col[(k0+lr)*NPIX + bm0 + lc .. +3]
        *reinterpret_cast<float4*>(&As[lr][lc]) =
            *reinterpret_cast<const float4*>(&g_col[(size_t)(k0 + lr) * NPIX + bm0 + lc]);
        // load B tile: g_wt[(k0+lr)*OC + bn0 + lc .. +3]
        *reinterpret_cast<float4*>(&Bs[lr][lc]) =
            *reinterpret_cast<const float4*>(&g_wt[(size_t)(k0 + lr) * OC + bn0 + lc]);
        __syncthreads();

        #pragma unroll
        for (int k = 0; k < 8; k++) {
            float a[8], b[8];
            *reinterpret_cast<float4*>(&a[0]) = *reinterpret_cast<const float4*>(&As[k][ty*8 + 0]);
            *reinterpret_cast<float4*>(&a[4]) = *reinterpret_cast<const float4*>(&As[k][ty*8 + 4]);
            *reinterpret_cast<float4*>(&b[0]) = *reinterpret_cast<const float4*>(&Bs[k][tx*8 + 0]);
            *reinterpret_cast<float4*>(&b[4]) = *reinterpret_cast<const float4*>(&Bs[k][tx*8 + 4]);
            #pragma unroll
            for (int i = 0; i < 8; i++)
                #pragma unroll
                for (int j = 0; j < 8; j++)
                    acc[i][j] += a[i] * b[j];
        }
        __syncthreads();
    }

    // write out: out[n][oc][hw], p = n*4096 + hw
    #pragma unroll
    for (int i = 0; i < 8; i++) {
        int p  = bm0 + ty * 8 + i;
        int nn = p >> 12;
        int hw = p & 4095;
        #pragma unroll
        for (int j = 0; j < 8; j++) {
            int oc = bn0 + tx * 8 + j;
            out[((size_t)(nn * OC + oc) << 12) + hw] = acc[i][j];
        }
    }
}

// ---------------------------------------------------------------------------
extern "C" void kernel_launch(void* const* d_in, const int* in_sizes, int n_in,
                              void* d_out, int out_size)
{
    const float* x  = (const float*)d_in[0];   // [4,256,64,64]
    const float* ow = (const float*)d_in[1];   // [27,256,3,3]
    const float* ob = (const float*)d_in[2];   // [27]
    const float* dw = (const float*)d_in[3];   // [256,256,3,3]
    float* out = (float*)d_out;                // [4,256,64,64]

    offset_conv_kernel<<<dim3(H_IM, OMC, N_B), 64>>>(x, ow, ob);
    reorder_w_kernel<<<dim3(KDIM), OC>>>(dw);
    sample_kernel<<<dim3(H_IM, N_B, 2), 256>>>(x);
    gemm_kernel<<<dim3(NPIX / 128, OC / 128), 256>>>(out);
}

// round 3
// speedup vs baseline: 2.4039x; 2.4039x over previous
#include <cuda_runtime.h>
#include <cuda_bf16.h>
#include <cstdint>

// Problem constants
#define N_B   4
#define C_IN  256
#define H_IM  64
#define W_IM  64
#define OC    256
#define K2    9
#define OMC   27
#define HW    (H_IM*W_IM)        // 4096
#define NPIX  (N_B*HW)           // 16384
#define KDIM  (C_IN*K2)          // 2304

// ---------------- device scratch (allocation-free rule) ----------------
__device__ float         g_om  [(size_t)N_B * OMC * HW];
__device__ float         g_part[(size_t)4 * N_B * OMC * HW];
__device__ unsigned int  g_colP[(size_t)KDIM * NPIX];            // packed (hi,lo) bf16 [kc][p]
__device__ __nv_bfloat16 g_colT_hi[(size_t)NPIX * KDIM];         // [p][kc]
__device__ __nv_bfloat16 g_colT_lo[(size_t)NPIX * KDIM];
__device__ __nv_bfloat16 g_wt_hi[(size_t)OC * KDIM];             // [oc][kc]
__device__ __nv_bfloat16 g_wt_lo[(size_t)OC * KDIM];

__device__ __forceinline__ uint32_t pack_split(float v) {
    __nv_bfloat16 h = __float2bfloat16(v);
    float lof = v - __bfloat162float(h);
    __nv_bfloat16 l = __float2bfloat16(lof);
    return (uint32_t)__bfloat16_as_ushort(h) | ((uint32_t)__bfloat16_as_ushort(l) << 16);
}

// ---------------------------------------------------------------------------
// Offset conv: grid (64 ho, 4 n, 4 cg); block 256 = 4 sub x 64 wo.
// ---------------------------------------------------------------------------
__global__ void offset_conv_kernel(const float* __restrict__ x,
                                   const float* __restrict__ ow)
{
    extern __shared__ float smf[];
    float* sw  = smf;                 // [64 c][27 oc][12]
    float* red = smf + 64 * 324;      // [4 sub][27 oc][64 wo]

    const int ho = blockIdx.x, n = blockIdx.y, cg = blockIdx.z;
    const int tid = threadIdx.x;
    const int wo = tid & 63, sub = tid >> 6;

    for (int idx = tid; idx < 64 * 324; idx += 256) {
        int c = idx / 324, r = idx % 324, oc = r / 12, k = r % 12;
        sw[idx] = (k < 9) ? ow[(size_t)oc * KDIM + (cg * 64 + c) * 9 + k] : 0.f;
    }
    __syncthreads();

    float acc[27];
    #pragma unroll
    for (int o = 0; o < 27; o++) acc[o] = 0.f;

    for (int i = 0; i < 16; i++) {
        int cl = sub * 16 + i;
        int c  = cg * 64 + cl;
        const float* xr = x + ((size_t)(n * C_IN + c) << 12);
        float xv[9];
        #pragma unroll
        for (int ky = 0; ky < 3; ky++) {
            int hy = ho + ky - 1;
            bool vy = (unsigned)hy < (unsigned)H_IM;
            const float* row = xr + (hy << 6);
            xv[ky*3+0] = (vy && wo >= 1)  ? row[wo-1] : 0.f;
            xv[ky*3+1] = vy               ? row[wo]   : 0.f;
            xv[ky*3+2] = (vy && wo <= 62) ? row[wo+1] : 0.f;
        }
        const float* wc = sw + cl * 324;
        #pragma unroll
        for (int o = 0; o < 27; o++) {
            float4 w0 = *reinterpret_cast<const float4*>(wc + o*12 + 0);
            float4 w1 = *reinterpret_cast<const float4*>(wc + o*12 + 4);
            float  w8 = wc[o*12 + 8];
            acc[o] += xv[0]*w0.x + xv[1]*w0.y + xv[2]*w0.z + xv[3]*w0.w
                    + xv[4]*w1.x + xv[5]*w1.y + xv[6]*w1.z + xv[7]*w1.w
                    + xv[8]*w8;
        }
    }
    #pragma unroll
    for (int o = 0; o < 27; o++) red[(sub * 27 + o) * 64 + wo] = acc[o];
    __syncthreads();

    for (int idx = tid; idx < 27 * 64; idx += 256) {
        int o = idx >> 6, w2 = idx & 63;
        float s = red[(0*27+o)*64+w2] + red[(1*27+o)*64+w2]
                + red[(2*27+o)*64+w2] + red[(3*27+o)*64+w2];
        g_part[(((size_t)cg * N_B + n) * OMC + o) * HW + (ho << 6) + w2] = s;
    }
}

__global__ void reduce_om_kernel(const float* __restrict__ ob)
{
    int idx = blockIdx.x * 256 + threadIdx.x;
    int oc = (idx >> 12) % OMC;
    size_t stride = (size_t)N_B * OMC * HW;
    g_om[idx] = ob[oc] + g_part[idx] + g_part[idx + stride]
              + g_part[idx + 2*stride] + g_part[idx + 3*stride];
}

// ---------------------------------------------------------------------------
// Weight reorder + split: g_wt_{hi,lo}[oc][k*256+c]
// ---------------------------------------------------------------------------
__global__ void reorder_w_kernel(const float* __restrict__ dw)
{
    int oc = blockIdx.x;
    int c  = threadIdx.x;
    #pragma unroll
    for (int k = 0; k < 9; k++) {
        float w = dw[((size_t)oc * C_IN + c) * K2 + k];
        uint32_t pk = pack_split(w);
        size_t o = (size_t)oc * KDIM + k * C_IN + c;
        g_wt_hi[o] = __ushort_as_bfloat16((unsigned short)(pk & 0xffff));
        g_wt_lo[o] = __ushort_as_bfloat16((unsigned short)(pk >> 16));
    }
}

// ---------------------------------------------------------------------------
// Bilinear sampling -> g_colP[kc][p] packed (hi,lo) bf16
// ---------------------------------------------------------------------------
__global__ void sample_kernel(const float* __restrict__ x)
{
    const int ho   = blockIdx.x;
    const int n    = blockIdx.y;
    const int half = blockIdx.z;
    const int tid  = threadIdx.x;

    __shared__ float s_w[K2][4][64];
    __shared__ int   s_idx[K2][4][64];

    for (int it = tid; it < 64 * K2; it += 256) {
        int k  = it / 64;
        int wo = it % 64;
        int p  = (ho << 6) + wo;
        const float* omn = g_om + (size_t)n * OMC * HW;

        float oy = omn[((size_t)(2*k    ) << 12) + p];
        float ox = omn[((size_t)(2*k + 1) << 12) + p];
        float mv = omn[((size_t)(18 + k ) << 12) + p];
        float m  = 1.0f / (1.0f + expf(-mv));

        float him = (float)(ho + (k / 3) - 1) + oy;
        float wim = (float)(wo + (k % 3) - 1) + ox;

        float y0 = floorf(him), x0 = floorf(wim);
        float lh = him - y0,    lw = wim - x0;
        float hh = 1.0f - lh,   hw = 1.0f - lw;
        float y1 = y0 + 1.0f,   x1 = x0 + 1.0f;

        float vy0 = (y0 >= 0.f && y0 <= 63.f) ? 1.f : 0.f;
        float vy1 = (y1 >= 0.f && y1 <= 63.f) ? 1.f : 0.f;
        float vx0 = (x0 >= 0.f && x0 <= 63.f) ? 1.f : 0.f;
        float vx1 = (x1 >= 0.f && x1 <= 63.f) ? 1.f : 0.f;

        int iy0 = (int)fminf(fmaxf(y0, 0.f), 63.f);
        int iy1 = (int)fminf(fmaxf(y1, 0.f), 63.f);
        int ix0 = (int)fminf(fmaxf(x0, 0.f), 63.f);
        int ix1 = (int)fminf(fmaxf(x1, 0.f), 63.f);

        s_w[k][0][wo] = hh * hw * m * vy0 * vx0;  s_idx[k][0][wo] = iy0 * 64 + ix0;
        s_w[k][1][wo] = hh * lw * m * vy0 * vx1;  s_idx[k][1][wo] = iy0 * 64 + ix1;
        s_w[k][2][wo] = lh * hw * m * vy1 * vx0;  s_idx[k][2][wo] = iy1 * 64 + ix0;
        s_w[k][3][wo] = lh * lw * m * vy1 * vx1;  s_idx[k][3][wo] = iy1 * 64 + ix1;
    }
    __syncthreads();

    const int wo = tid & 63;
    const int cq = tid >> 6;
    const size_t pcol = (size_t)n * HW + (ho << 6) + wo;

    float wreg[36];
    int   ireg[36];
    #pragma unroll
    for (int k = 0; k < K2; k++)
        #pragma unroll
        for (int j = 0; j < 4; j++) {
            wreg[k*4+j] = s_w[k][j][wo];
            ireg[k*4+j] = s_idx[k][j][wo];
        }

    for (int ci = 0; ci < 32; ci++) {
        int c = half * 128 + ci * 4 + cq;
        const float* xb = x + ((size_t)(n * C_IN + c) << 12);
        #pragma unroll
        for (int k = 0; k < K2; k++) {
            float v = wreg[k*4+0] * xb[ireg[k*4+0]]
                    + wreg[k*4+1] * xb[ireg[k*4+1]]
                    + wreg[k*4+2] * xb[ireg[k*4+2]]
                    + wreg[k*4+3] * xb[ireg[k*4+3]];
            g_colP[(size_t)(k * C_IN + c) * NPIX + pcol] = pack_split(v);
        }
    }
}

// ---------------------------------------------------------------------------
// Transpose packed [kc][p] -> bf16 planes [p][kc]
// ---------------------------------------------------------------------------
__global__ void transpose_kernel()
{
    __shared__ unsigned int ts[64][65];
    const int kc0 = blockIdx.x * 64;
    const int p0  = blockIdx.y * 64;
    const int tid = threadIdx.x;

    #pragma unroll
    for (int it = 0; it < 16; it++) {
        int idx = tid + it * 256;
        int r = idx >> 6, c = idx & 63;
        ts[r][c] = g_colP[(size_t)(kc0 + r) * NPIX + p0 + c];
    }
    __syncthreads();
    #pragma unroll
    for (int it = 0; it < 16; it++) {
        int idx = tid + it * 256;
        int pr = idx >> 6, kcc = idx & 63;
        unsigned int v = ts[kcc][pr];
        size_t o = (size_t)(p0 + pr) * KDIM + kc0 + kcc;
        g_colT_hi[o] = __ushort_as_bfloat16((unsigned short)(v & 0xffff));
        g_colT_lo[o] = __ushort_as_bfloat16((unsigned short)(v >> 16));
    }
}

// ---------------------------------------------------------------------------
// mma.sync bf16 GEMM with 3-term split precision.
// D[64 px, 256 oc] per CTA.  A: colT planes [p][kc], B: wt planes [oc][kc].
// BK=32, cp.async double-buffered. 8 warps = 2(M) x 4(N); warp tile 32x64.
// ---------------------------------------------------------------------------
#define BK        32
#define NSTAGE_IT (KDIM / BK)          // 72
#define ROWB      80                   // padded smem row stride (bytes) for 32 bf16
#define A_PLANE   (64 * ROWB)          // 5120
#define B_PLANE   (256 * ROWB)         // 20480
#define STG_SZ    (2*A_PLANE + 2*B_PLANE)   // 51200
#define GEMM_SMEM (2 * STG_SZ)              // 102400

__device__ __forceinline__ void cp16(uint32_t dst, const void* src) {
    asm volatile("cp.async.cg.shared.global [%0], [%1], 16;\n" :: "r"(dst), "l"(src));
}
__device__ __forceinline__ void mma_bf16(float* c, const uint32_t* a, const uint32_t* b) {
    asm volatile(
        "mma.sync.aligned.m16n8k16.row.col.f32.bf16.bf16.f32 "
        "{%0,%1,%2,%3}, {%4,%5,%6,%7}, {%8,%9}, {%0,%1,%2,%3};"
        : "+f"(c[0]), "+f"(c[1]), "+f"(c[2]), "+f"(c[3])
        : "r"(a[0]), "r"(a[1]), "r"(a[2]), "r"(a[3]), "r"(b[0]), "r"(b[1]));
}

__global__ void __launch_bounds__(256, 2) gemm_mma_kernel(float* __restrict__ out)
{
    extern __shared__ char sm[];
    const uint32_t sb = (uint32_t)__cvta_generic_to_shared(sm);
    const int tid = threadIdx.x;
    const int wid = tid >> 5;
    const int lid = tid & 31;
    const int bm0 = blockIdx.x * 64;

    const int warpM = wid & 1;         // 0..1
    const int warpN = wid >> 1;        // 0..3

    float acc[2][8][4];
    #pragma unroll
    for (int i = 0; i < 2; i++)
        #pragma unroll
        for (int j = 0; j < 8; j++)
            #pragma unroll
            for (int q = 0; q < 4; q++) acc[i][j][q] = 0.f;

    // stage layout: [Ahi | Alo | Bhi | Blo]
    auto load_stage = [&](int st, int ch) {
        const int k0 = ch * BK;
        const uint32_t base = sb + st * STG_SZ;
        // A: 64 rows x 4 chunks x 2 planes = 512 ops, 2 iters
        {
            int idx = tid;               // plane hi
            int row = idx >> 2, q = idx & 3;
            cp16(base + row * ROWB + q * 16,
                 g_colT_hi + (size_t)(bm0 + row) * KDIM + k0 + q * 8);
            cp16(base + A_PLANE + row * ROWB + q * 16,
                 g_colT_lo + (size_t)(bm0 + row) * KDIM + k0 + q * 8);
        }
        // B: 256 rows x 4 chunks x 2 planes = 2048 ops, 8 iters
        #pragma unroll
        for (int it = 0; it < 4; it++) {
            int idx = tid + it * 256;
            int row = idx >> 2, q = idx & 3;
            cp16(base + 2*A_PLANE + row * ROWB + q * 16,
                 g_wt_hi + (size_t)row * KDIM + k0 + q * 8);
            cp16(base + 2*A_PLANE + B_PLANE + row * ROWB + q * 16,
                 g_wt_lo + (size_t)row * KDIM + k0 + q * 8);
        }
        asm volatile("cp.async.commit_group;\n" ::: "memory");
    };

    load_stage(0, 0);

    for (int ch = 0; ch < NSTAGE_IT; ch++) {
        const int st = ch & 1;
        if (ch + 1 < NSTAGE_IT) {
            load_stage(st ^ 1, ch + 1);
            asm volatile("cp.async.wait_group 1;\n" ::: "memory");
        } else {
            asm volatile("cp.async.wait_group 0;\n" ::: "memory");
        }
        __syncthreads();

        const uint32_t base = sb + st * STG_SZ;
        const uint32_t aoff = (warpM * 32 + (lid >> 2)) * ROWB + (lid & 3) * 4;
        const uint32_t boff = (warpN * 64 + (lid >> 2)) * ROWB + (lid & 3) * 4;

        #pragma unroll
        for (int kp = 0; kp < 2; kp++) {
            const uint32_t kpo = kp * 32;
            uint32_t Ah[2][4], Al[2][4], Bh[8][2], Bl[8][2];
            #pragma unroll
            for (int i = 0; i < 2; i++) {
                uint32_t r0 = base + aoff + i * (16 * ROWB) + kpo;
                Ah[i][0] = *(const uint32_t*)(sm + (r0            - sb));
                Ah[i][1] = *(const uint32_t*)(sm + (r0 + 8*ROWB   - sb));
                Ah[i][2] = *(const uint32_t*)(sm + (r0 + 16       - sb));
                Ah[i][3] = *(const uint32_t*)(sm + (r0 + 8*ROWB+16 - sb));
                uint32_t r1 = r0 + A_PLANE;
                Al[i][0] = *(const uint32_t*)(sm + (r1            - sb));
                Al[i][1] = *(const uint32_t*)(sm + (r1 + 8*ROWB   - sb));
                Al[i][2] = *(const uint32_t*)(sm + (r1 + 16       - sb));
                Al[i][3] = *(const uint32_t*)(sm + (r1 + 8*ROWB+16 - sb));
            }
            #pragma unroll
            for (int j = 0; j < 8; j++) {
                uint32_t r0 = base + 2*A_PLANE + boff + j * (8 * ROWB) + kpo;
                Bh[j][0] = *(const uint32_t*)(sm + (r0      - sb));
                Bh[j][1] = *(const uint32_t*)(sm + (r0 + 16 - sb));
                uint32_t r1 = r0 + B_PLANE;
                Bl[j][0] = *(const uint32_t*)(sm + (r1      - sb));
                Bl[j][1] = *(const uint32_t*)(sm + (r1 + 16 - sb));
            }
            // term 1: Ah*Bh ; term 2: Ah*Bl ; term 3: Al*Bh  (reuse distance 16)
            #pragma unroll
            for (int j = 0; j < 8; j++) {
                mma_bf16(acc[0][j], Ah[0], Bh[j]);
                mma_bf16(acc[1][j], Ah[1], Bh[j]);
            }
            #pragma unroll
            for (int j = 0; j < 8; j++) {
                mma_bf16(acc[0][j], Ah[0], Bl[j]);
                mma_bf16(acc[1][j], Ah[1], Bl[j]);
            }
            #pragma unroll
            for (int j = 0; j < 8; j++) {
                mma_bf16(acc[0][j], Al[0], Bh[j]);
                mma_bf16(acc[1][j], Al[1], Bh[j]);
            }
        }
        __syncthreads();
    }

    // ---- epilogue: smem transpose [oc][m] (stride 68 floats), coalesced store
    float* T = (float*)sm;
    #pragma unroll
    for (int i = 0; i < 2; i++) {
        int row0 = warpM * 32 + i * 16 + (lid >> 2);
        #pragma unroll
        for (int j = 0; j < 8; j++) {
            int ocl = warpN * 64 + j * 8 + (lid & 3) * 2;
            T[ ocl      * 68 + row0    ] = acc[i][j][0];
            T[(ocl + 1) * 68 + row0    ] = acc[i][j][1];
            T[ ocl      * 68 + row0 + 8] = acc[i][j][2];
            T[(ocl + 1) * 68 + row0 + 8] = acc[i][j][3];
        }
    }
    __syncthreads();

    const int n   = bm0 >> 12;
    const int hwb = bm0 & 4095;
    #pragma unroll
    for (int it = 0; it < 64; it++) {
        int idx = tid + it * 256;
        int oc = idx >> 6, m = idx & 63;
        out[((size_t)(n * OC + oc) << 12) + hwb + m] = T[oc * 68 + m];
    }
}

// ---------------------------------------------------------------------------
extern "C" void kernel_launch(void* const* d_in, const int* in_sizes, int n_in,
                              void* d_out, int out_size)
{
    const float* x  = (const float*)d_in[0];
    const float* ow = (const float*)d_in[1];
    const float* ob = (const float*)d_in[2];
    const float* dw = (const float*)d_in[3];
    float* out = (float*)d_out;

    cudaFuncSetAttribute(offset_conv_kernel,
        cudaFuncAttributeMaxDynamicSharedMemorySize, 64*324*4 + 4*27*64*4);
    cudaFuncSetAttribute(gemm_mma_kernel,
        cudaFuncAttributeMaxDynamicSharedMemorySize, GEMM_SMEM);

    offset_conv_kernel<<<dim3(H_IM, N_B, 4), 256, 64*324*4 + 4*27*64*4>>>(x, ow);
    reduce_om_kernel<<<(N_B*OMC*HW)/256, 256>>>(ob);
    reorder_w_kernel<<<OC, C_IN>>>(dw);
    sample_kernel<<<dim3(H_IM, N_B, 2), 256>>>(x);
    transpose_kernel<<<dim3(KDIM/64, NPIX/64), 256>>>();
    gemm_mma_kernel<<<NPIX/64, 256, GEMM_SMEM>>>(out);
}

// round 4
// speedup vs baseline: 4.0868x; 1.7000x over previous
#include <cuda_runtime.h>
#include <cuda_fp16.h>
#include <cstdint>

// Problem constants
#define N_B   4
#define C_IN  256
#define H_IM  64
#define W_IM  64
#define OC    256
#define K2    9
#define OMC   27
#define HW    (H_IM*W_IM)        // 4096
#define NPIX  (N_B*HW)           // 16384
#define KDIM  (C_IN*K2)          // 2304

// ---------------- device scratch (allocation-free rule) ----------------
__device__ float  g_om  [(size_t)N_B * OMC * HW];
__device__ float  g_part[(size_t)4 * N_B * OMC * HW];
__device__ __half g_colF[(size_t)KDIM * NPIX];     // fp16 im2col [kc][p]
__device__ __half g_wtF [(size_t)OC * KDIM];       // fp16 weights [oc][kc]

// ---------------------------------------------------------------------------
// Offset conv: grid (64 ho, 4 n, 4 cg); block 256 = 4 sub x 64 wo.
// ---------------------------------------------------------------------------
__global__ void offset_conv_kernel(const float* __restrict__ x,
                                   const float* __restrict__ ow)
{
    extern __shared__ float smf[];
    float* sw  = smf;                 // [64 c][27 oc][12]
    float* red = smf + 64 * 324;      // [4 sub][27 oc][64 wo]

    const int ho = blockIdx.x, n = blockIdx.y, cg = blockIdx.z;
    const int tid = threadIdx.x;
    const int wo = tid & 63, sub = tid >> 6;

    for (int idx = tid; idx < 64 * 324; idx += 256) {
        int c = idx / 324, r = idx % 324, oc = r / 12, k = r % 12;
        sw[idx] = (k < 9) ? ow[(size_t)oc * KDIM + (cg * 64 + c) * 9 + k] : 0.f;
    }
    __syncthreads();

    float acc[27];
    #pragma unroll
    for (int o = 0; o < 27; o++) acc[o] = 0.f;

    for (int i = 0; i < 16; i++) {
        int cl = sub * 16 + i;
        int c  = cg * 64 + cl;
        const float* xr = x + ((size_t)(n * C_IN + c) << 12);
        float xv[9];
        #pragma unroll
        for (int ky = 0; ky < 3; ky++) {
            int hy = ho + ky - 1;
            bool vy = (unsigned)hy < (unsigned)H_IM;
            const float* row = xr + (hy << 6);
            xv[ky*3+0] = (vy && wo >= 1)  ? row[wo-1] : 0.f;
            xv[ky*3+1] = vy               ? row[wo]   : 0.f;
            xv[ky*3+2] = (vy && wo <= 62) ? row[wo+1] : 0.f;
        }
        const float* wc = sw + cl * 324;
        #pragma unroll
        for (int o = 0; o < 27; o++) {
            float4 w0 = *reinterpret_cast<const float4*>(wc + o*12 + 0);
            float4 w1 = *reinterpret_cast<const float4*>(wc + o*12 + 4);
            float  w8 = wc[o*12 + 8];
            acc[o] += xv[0]*w0.x + xv[1]*w0.y + xv[2]*w0.z + xv[3]*w0.w
                    + xv[4]*w1.x + xv[5]*w1.y + xv[6]*w1.z + xv[7]*w1.w
                    + xv[8]*w8;
        }
    }
    #pragma unroll
    for (int o = 0; o < 27; o++) red[(sub * 27 + o) * 64 + wo] = acc[o];
    __syncthreads();

    for (int idx = tid; idx < 27 * 64; idx += 256) {
        int o = idx >> 6, w2 = idx & 63;
        float s = red[(0*27+o)*64+w2] + red[(1*27+o)*64+w2]
                + red[(2*27+o)*64+w2] + red[(3*27+o)*64+w2];
        g_part[(((size_t)cg * N_B + n) * OMC + o) * HW + (ho << 6) + w2] = s;
    }
}

__global__ void reduce_om_kernel(const float* __restrict__ ob)
{
    int idx = blockIdx.x * 256 + threadIdx.x;
    int oc = (idx >> 12) % OMC;
    size_t stride = (size_t)N_B * OMC * HW;
    g_om[idx] = ob[oc] + g_part[idx] + g_part[idx + stride]
              + g_part[idx + 2*stride] + g_part[idx + 3*stride];
}

// ---------------------------------------------------------------------------
// Weight reorder to fp16: g_wtF[oc][k*256+c]
// ---------------------------------------------------------------------------
__global__ void reorder_w_kernel(const float* __restrict__ dw)
{
    int oc = blockIdx.x;
    int c  = threadIdx.x;
    #pragma unroll
    for (int k = 0; k < 9; k++) {
        float w = dw[((size_t)oc * C_IN + c) * K2 + k];
        g_wtF[(size_t)oc * KDIM + k * C_IN + c] = __float2half_rn(w);
    }
}

// ---------------------------------------------------------------------------
// Bilinear sampling -> g_colF[kc][p] fp16
// ---------------------------------------------------------------------------
__global__ void sample_kernel(const float* __restrict__ x)
{
    const int ho   = blockIdx.x;
    const int n    = blockIdx.y;
    const int half = blockIdx.z;
    const int tid  = threadIdx.x;

    __shared__ float s_w[K2][4][64];
    __shared__ int   s_idx[K2][4][64];

    for (int it = tid; it < 64 * K2; it += 256) {
        int k  = it / 64;
        int wo = it % 64;
        int p  = (ho << 6) + wo;
        const float* omn = g_om + (size_t)n * OMC * HW;

        float oy = omn[((size_t)(2*k    ) << 12) + p];
        float ox = omn[((size_t)(2*k + 1) << 12) + p];
        float mv = omn[((size_t)(18 + k ) << 12) + p];
        float m  = 1.0f / (1.0f + expf(-mv));

        float him = (float)(ho + (k / 3) - 1) + oy;
        float wim = (float)(wo + (k % 3) - 1) + ox;

        float y0 = floorf(him), x0 = floorf(wim);
        float lh = him - y0,    lw = wim - x0;
        float hh = 1.0f - lh,   hw = 1.0f - lw;
        float y1 = y0 + 1.0f,   x1 = x0 + 1.0f;

        float vy0 = (y0 >= 0.f && y0 <= 63.f) ? 1.f : 0.f;
        float vy1 = (y1 >= 0.f && y1 <= 63.f) ? 1.f : 0.f;
        float vx0 = (x0 >= 0.f && x0 <= 63.f) ? 1.f : 0.f;
        float vx1 = (x1 >= 0.f && x1 <= 63.f) ? 1.f : 0.f;

        int iy0 = (int)fminf(fmaxf(y0, 0.f), 63.f);
        int iy1 = (int)fminf(fmaxf(y1, 0.f), 63.f);
        int ix0 = (int)fminf(fmaxf(x0, 0.f), 63.f);
        int ix1 = (int)fminf(fmaxf(x1, 0.f), 63.f);

        s_w[k][0][wo] = hh * hw * m * vy0 * vx0;  s_idx[k][0][wo] = iy0 * 64 + ix0;
        s_w[k][1][wo] = hh * lw * m * vy0 * vx1;  s_idx[k][1][wo] = iy0 * 64 + ix1;
        s_w[k][2][wo] = lh * hw * m * vy1 * vx0;  s_idx[k][2][wo] = iy1 * 64 + ix0;
        s_w[k][3][wo] = lh * lw * m * vy1 * vx1;  s_idx[k][3][wo] = iy1 * 64 + ix1;
    }
    __syncthreads();

    const int wo = tid & 63;
    const int cq = tid >> 6;
    const size_t pcol = (size_t)n * HW + (ho << 6) + wo;

    float wreg[36];
    int   ireg[36];
    #pragma unroll
    for (int k = 0; k < K2; k++)
        #pragma unroll
        for (int j = 0; j < 4; j++) {
            wreg[k*4+j] = s_w[k][j][wo];
            ireg[k*4+j] = s_idx[k][j][wo];
        }

    for (int ci = 0; ci < 32; ci++) {
        int c = half * 128 + ci * 4 + cq;
        const float* xb = x + ((size_t)(n * C_IN + c) << 12);
        #pragma unroll
        for (int k = 0; k < K2; k++) {
            float v = wreg[k*4+0] * xb[ireg[k*4+0]]
                    + wreg[k*4+1] * xb[ireg[k*4+1]]
                    + wreg[k*4+2] * xb[ireg[k*4+2]]
                    + wreg[k*4+3] * xb[ireg[k*4+3]];
            g_colF[(size_t)(k * C_IN + c) * NPIX + pcol] = __float2half_rn(v);
        }
    }
}

// ---------------------------------------------------------------------------
// fp16 mma.sync GEMM: D[128 px, 256 oc] per CTA, single term.
// A staged [32 kc][128 px] (pitch 272B) -> ldmatrix.x4.trans
// B staged [256 oc][32 kc] (pitch 80B)  -> ldmatrix.x4
// 8 warps = 2(M) x 4(N); warp tile 64x64; BK=32, double-buffered cp.async.
// ---------------------------------------------------------------------------
#define BK      32
#define NITER   (KDIM / BK)       // 72
#define APITCH  272
#define BPITCH  80
#define A_SZ    (BK * APITCH)     // 8704
#define B_SZ    (256 * BPITCH)    // 20480
#define STG     (A_SZ + B_SZ)     // 29184
#define GEMM_SMEM (2 * STG)       // 58368

__device__ __forceinline__ void cp16(uint32_t dst, const void* src) {
    asm volatile("cp.async.cg.shared.global [%0], [%1], 16;\n" :: "r"(dst), "l"(src));
}
__device__ __forceinline__ void ldmx4(uint32_t* r, uint32_t addr) {
    asm volatile("ldmatrix.sync.aligned.m8n8.x4.shared.b16 {%0,%1,%2,%3}, [%4];"
        : "=r"(r[0]), "=r"(r[1]), "=r"(r[2]), "=r"(r[3]) : "r"(addr));
}
__device__ __forceinline__ void ldmx4t(uint32_t* r, uint32_t addr) {
    asm volatile("ldmatrix.sync.aligned.m8n8.x4.trans.shared.b16 {%0,%1,%2,%3}, [%4];"
        : "=r"(r[0]), "=r"(r[1]), "=r"(r[2]), "=r"(r[3]) : "r"(addr));
}
__device__ __forceinline__ void mma_f16(float* c, const uint32_t* a, const uint32_t* b) {
    asm volatile(
        "mma.sync.aligned.m16n8k16.row.col.f32.f16.f16.f32 "
        "{%0,%1,%2,%3}, {%4,%5,%6,%7}, {%8,%9}, {%0,%1,%2,%3};"
        : "+f"(c[0]), "+f"(c[1]), "+f"(c[2]), "+f"(c[3])
        : "r"(a[0]), "r"(a[1]), "r"(a[2]), "r"(a[3]), "r"(b[0]), "r"(b[1]));
}

__global__ void __launch_bounds__(256, 1) gemm_mma_kernel(float* __restrict__ out)
{
    extern __shared__ char sm[];
    const uint32_t sb = (uint32_t)__cvta_generic_to_shared(sm);
    const int tid = threadIdx.x;
    const int wid = tid >> 5;
    const int lid = tid & 31;
    const int bm0 = blockIdx.x * 128;

    const int warpM = wid & 1;         // 0..1
    const int warpN = wid >> 1;        // 0..3

    float acc[4][8][4];
    #pragma unroll
    for (int i = 0; i < 4; i++)
        #pragma unroll
        for (int j = 0; j < 8; j++)
            #pragma unroll
            for (int q = 0; q < 4; q++) acc[i][j][q] = 0.f;

    auto load_stage = [&](int st, int ch) {
        const int k0 = ch * BK;
        const uint32_t ab = sb + st * STG;
        const uint32_t bb = ab + A_SZ;
        // A: 32 rows x 256B = 512 x 16B
        #pragma unroll
        for (int it = 0; it < 2; it++) {
            int idx = tid + it * 256;
            int row = idx >> 4, q = idx & 15;
            cp16(ab + row * APITCH + q * 16,
                 g_colF + (size_t)(k0 + row) * NPIX + bm0 + q * 8);
        }
        // B: 256 rows x 64B = 1024 x 16B
        #pragma unroll
        for (int it = 0; it < 4; it++) {
            int idx = tid + it * 256;
            int row = idx >> 2, q = idx & 3;
            cp16(bb + row * BPITCH + q * 16,
                 g_wtF + (size_t)row * KDIM + k0 + q * 8);
        }
        asm volatile("cp.async.commit_group;\n" ::: "memory");
    };

    // ldmatrix per-thread address components
    const int qq = lid >> 3;           // matrix index 0..3
    const int jr = lid & 7;            // row within matrix
    // A (trans): matrix q -> m_off = (q&1)*8, k_off = (q>>1)*8; row j = kc
    const uint32_t aoff = (uint32_t)(((qq >> 1) * 8 + jr) * APITCH
                                     + (warpM * 64 + (qq & 1) * 8) * 2);
    // B: matrix q -> n_off = (q>>1)*8, k_off = (q&1)*8; row j = oc
    const uint32_t boff = (uint32_t)((warpN * 64 + (qq >> 1) * 8 + jr) * BPITCH
                                     + (qq & 1) * 16);

    load_stage(0, 0);

    for (int ch = 0; ch < NITER; ch++) {
        const int st = ch & 1;
        if (ch + 1 < NITER) {
            load_stage(st ^ 1, ch + 1);
            asm volatile("cp.async.wait_group 1;\n" ::: "memory");
        } else {
            asm volatile("cp.async.wait_group 0;\n" ::: "memory");
        }
        __syncthreads();

        const uint32_t ab = sb + st * STG;
        const uint32_t bb = ab + A_SZ;

        #pragma unroll
        for (int kp = 0; kp < 2; kp++) {
            uint32_t Af[4][4], Bf[4][4];
            #pragma unroll
            for (int mi = 0; mi < 4; mi++)
                ldmx4t(Af[mi], ab + aoff + kp * (16 * APITCH) + mi * 32);
            #pragma unroll
            for (int pi = 0; pi < 4; pi++)
                ldmx4(Bf[pi], bb + boff + pi * (16 * BPITCH) + kp * 32);

            #pragma unroll
            for (int mi = 0; mi < 4; mi++)
                #pragma unroll
                for (int pi = 0; pi < 4; pi++) {
                    mma_f16(acc[mi][pi*2],   Af[mi], &Bf[pi][0]);
                    mma_f16(acc[mi][pi*2+1], Af[mi], &Bf[pi][2]);
                }
        }
        __syncthreads();
    }

    // epilogue: direct stores (each oc row gets 8 consecutive px = full sectors)
    const int nIdx = bm0 >> 12;
    const int hwb  = bm0 & 4095;
    #pragma unroll
    for (int mi = 0; mi < 4; mi++) {
        int r = hwb + warpM * 64 + mi * 16 + (lid >> 2);
        #pragma unroll
        for (int jj = 0; jj < 8; jj++) {
            int oc = warpN * 64 + jj * 8 + (lid & 3) * 2;
            size_t base = ((size_t)(nIdx * OC + oc) << 12);
            out[base + r]            = acc[mi][jj][0];
            out[base + 4096 + r]     = acc[mi][jj][1];
            out[base + r + 8]        = acc[mi][jj][2];
            out[base + 4096 + r + 8] = acc[mi][jj][3];
        }
    }
}

// ---------------------------------------------------------------------------
extern "C" void kernel_launch(void* const* d_in, const int* in_sizes, int n_in,
                              void* d_out, int out_size)
{
    const float* x  = (const float*)d_in[0];
    const float* ow = (const float*)d_in[1];
    const float* ob = (const float*)d_in[2];
    const float* dw = (const float*)d_in[3];
    float* out = (float*)d_out;

    cudaFuncSetAttribute(offset_conv_kernel,
        cudaFuncAttributeMaxDynamicSharedMemorySize, 64*324*4 + 4*27*64*4);
    cudaFuncSetAttribute(gemm_mma_kernel,
        cudaFuncAttributeMaxDynamicSharedMemorySize, GEMM_SMEM);

    offset_conv_kernel<<<dim3(H_IM, N_B, 4), 256, 64*324*4 + 4*27*64*4>>>(x, ow);
    reduce_om_kernel<<<(N_B*OMC*HW)/256, 256>>>(ob);
    reorder_w_kernel<<<OC, C_IN>>>(dw);
    sample_kernel<<<dim3(H_IM, N_B, 2), 256>>>(x);
    gemm_mma_kernel<<<NPIX/128, 256, GEMM_SMEM>>>(out);
}

// round 5
// speedup vs baseline: 4.3409x; 1.0622x over previous
#include <cuda_runtime.h>
#include <cuda_fp16.h>
#include <cstdint>

// Problem constants
#define N_B   4
#define C_IN  256
#define H_IM  64
#define W_IM  64
#define OC    256
#define K2    9
#define OMC   27
#define HW    (H_IM*W_IM)        // 4096
#define NPIX  (N_B*HW)           // 16384
#define KDIM  (C_IN*K2)          // 2304

// ---------------- device scratch ----------------
__device__ float  g_om  [(size_t)N_B * OMC * HW];
__device__ float  g_part[(size_t)4 * N_B * OMC * HW];
__device__ __half g_wtF [(size_t)OC * KDIM];       // fp16 weights [oc][kc]

// ---------------------------------------------------------------------------
// Offset conv: grid (64 ho, 4 n, 4 cg); block 256 = 4 sub x 64 wo.
// ---------------------------------------------------------------------------
__global__ void offset_conv_kernel(const float* __restrict__ x,
                                   const float* __restrict__ ow)
{
    extern __shared__ float smf[];
    float* sw  = smf;                 // [64 c][27 oc][12]
    float* red = smf + 64 * 324;      // [4 sub][27 oc][64 wo]

    const int ho = blockIdx.x, n = blockIdx.y, cg = blockIdx.z;
    const int tid = threadIdx.x;
    const int wo = tid & 63, sub = tid >> 6;

    for (int idx = tid; idx < 64 * 324; idx += 256) {
        int c = idx / 324, r = idx % 324, oc = r / 12, k = r % 12;
        sw[idx] = (k < 9) ? ow[(size_t)oc * KDIM + (cg * 64 + c) * 9 + k] : 0.f;
    }
    __syncthreads();

    float acc[27];
    #pragma unroll
    for (int o = 0; o < 27; o++) acc[o] = 0.f;

    for (int i = 0; i < 16; i++) {
        int cl = sub * 16 + i;
        int c  = cg * 64 + cl;
        const float* xr = x + ((size_t)(n * C_IN + c) << 12);
        float xv[9];
        #pragma unroll
        for (int ky = 0; ky < 3; ky++) {
            int hy = ho + ky - 1;
            bool vy = (unsigned)hy < (unsigned)H_IM;
            const float* row = xr + (hy << 6);
            xv[ky*3+0] = (vy && wo >= 1)  ? row[wo-1] : 0.f;
            xv[ky*3+1] = vy               ? row[wo]   : 0.f;
            xv[ky*3+2] = (vy && wo <= 62) ? row[wo+1] : 0.f;
        }
        const float* wc = sw + cl * 324;
        #pragma unroll
        for (int o = 0; o < 27; o++) {
            float4 w0 = *reinterpret_cast<const float4*>(wc + o*12 + 0);
            float4 w1 = *reinterpret_cast<const float4*>(wc + o*12 + 4);
            float  w8 = wc[o*12 + 8];
            acc[o] += xv[0]*w0.x + xv[1]*w0.y + xv[2]*w0.z + xv[3]*w0.w
                    + xv[4]*w1.x + xv[5]*w1.y + xv[6]*w1.z + xv[7]*w1.w
                    + xv[8]*w8;
        }
    }
    #pragma unroll
    for (int o = 0; o < 27; o++) red[(sub * 27 + o) * 64 + wo] = acc[o];
    __syncthreads();

    for (int idx = tid; idx < 27 * 64; idx += 256) {
        int o = idx >> 6, w2 = idx & 63;
        float s = red[(0*27+o)*64+w2] + red[(1*27+o)*64+w2]
                + red[(2*27+o)*64+w2] + red[(3*27+o)*64+w2];
        g_part[(((size_t)cg * N_B + n) * OMC + o) * HW + (ho << 6) + w2] = s;
    }
}

__global__ void reduce_om_kernel(const float* __restrict__ ob)
{
    int idx = blockIdx.x * 256 + threadIdx.x;
    int oc = (idx >> 12) % OMC;
    size_t stride = (size_t)N_B * OMC * HW;
    g_om[idx] = ob[oc] + g_part[idx] + g_part[idx + stride]
              + g_part[idx + 2*stride] + g_part[idx + 3*stride];
}

// ---------------------------------------------------------------------------
// Weight reorder to fp16: g_wtF[oc][k*256+c]
// ---------------------------------------------------------------------------
__global__ void reorder_w_kernel(const float* __restrict__ dw)
{
    int oc = blockIdx.x;
    int c  = threadIdx.x;
    #pragma unroll
    for (int k = 0; k < 9; k++) {
        float w = dw[((size_t)oc * C_IN + c) * K2 + k];
        g_wtF[(size_t)oc * KDIM + k * C_IN + c] = __float2half_rn(w);
    }
}

// ---------------------------------------------------------------------------
// Fused sample + fp16 mma GEMM.
// CTA: 128 px x 256 oc, K=2304 in 72 chunks of 32 (chunk ch: kc = ch*32..+31,
// i.e. tap k = ch/8, channels (ch%8)*32..+31 -- matches g_wtF K order).
// A tile [32 kc][128 px] built in smem by gather+lerp from x; B via cp.async.
// 512 threads = 16 warps (4M x 4N), warp tile 32x64.
// ---------------------------------------------------------------------------
#define BK      32
#define NITER   (KDIM / BK)       // 72
#define APITCH  272
#define BPITCH  80
#define A_SZ    (BK * APITCH)     // 8704
#define B_SZ    (256 * BPITCH)    // 20480
#define SW_OFF   0                // 9*128*16 = 18432
#define SIDX_OFF 18432            // 9*128*8  = 9216
#define A_OFF    27648            // 2 * 8704 = 17408
#define B_OFF    45056            // 2 * 20480 = 40960
#define FUSED_SMEM 86016

__device__ __forceinline__ void cp16(uint32_t dst, const void* src) {
    asm volatile("cp.async.cg.shared.global [%0], [%1], 16;\n" :: "r"(dst), "l"(src));
}
__device__ __forceinline__ void ldmx4(uint32_t* r, uint32_t addr) {
    asm volatile("ldmatrix.sync.aligned.m8n8.x4.shared.b16 {%0,%1,%2,%3}, [%4];"
        : "=r"(r[0]), "=r"(r[1]), "=r"(r[2]), "=r"(r[3]) : "r"(addr));
}
__device__ __forceinline__ void ldmx4t(uint32_t* r, uint32_t addr) {
    asm volatile("ldmatrix.sync.aligned.m8n8.x4.trans.shared.b16 {%0,%1,%2,%3}, [%4];"
        : "=r"(r[0]), "=r"(r[1]), "=r"(r[2]), "=r"(r[3]) : "r"(addr));
}
__device__ __forceinline__ void mma_f16(float* c, const uint32_t* a, const uint32_t* b) {
    asm volatile(
        "mma.sync.aligned.m16n8k16.row.col.f32.f16.f16.f32 "
        "{%0,%1,%2,%3}, {%4,%5,%6,%7}, {%8,%9}, {%0,%1,%2,%3};"
        : "+f"(c[0]), "+f"(c[1]), "+f"(c[2]), "+f"(c[3])
        : "r"(a[0]), "r"(a[1]), "r"(a[2]), "r"(a[3]), "r"(b[0]), "r"(b[1]));
}
__device__ __forceinline__ void sts16(uint32_t addr, unsigned short v) {
    asm volatile("st.shared.u16 [%0], %1;" :: "r"(addr), "h"(v));
}

__global__ void __launch_bounds__(512, 1) fused_gemm_kernel(
    const float* __restrict__ x, float* __restrict__ out)
{
    extern __shared__ char sm[];
    const uint32_t sb = (uint32_t)__cvta_generic_to_shared(sm);
    float4* swp = (float4*)(sm + SW_OFF);     // [9*128] corner weights
    uint2*  sip = (uint2*)(sm + SIDX_OFF);    // [9*128] packed corner indices

    const int tid = threadIdx.x;
    const int wid = tid >> 5, lid = tid & 31;
    const int warpM = wid & 3, warpN = wid >> 2;
    const int bm0 = blockIdx.x * 128;
    const int nIdx = bm0 >> 12, hwb = bm0 & 4095;
    const int ho0 = hwb >> 6;

    // ---- prologue: bilinear weights/indices for 128 px x 9 taps ----
    for (int t = tid; t < 9 * 128; t += 512) {
        int k = t >> 7, pl = t & 127;
        int ho = ho0 + (pl >> 6), wo = pl & 63;
        int p = (ho << 6) + wo;
        const float* omn = g_om + (size_t)nIdx * OMC * HW;
        float oy = omn[((size_t)(2*k    ) << 12) + p];
        float ox = omn[((size_t)(2*k + 1) << 12) + p];
        float mv = omn[((size_t)(18 + k ) << 12) + p];
        float m  = 1.0f / (1.0f + expf(-mv));
        float him = (float)(ho + (k / 3) - 1) + oy;
        float wim = (float)(wo + (k % 3) - 1) + ox;
        float y0 = floorf(him), x0 = floorf(wim);
        float lh = him - y0,    lw = wim - x0;
        float hh = 1.0f - lh,   hw = 1.0f - lw;
        float y1 = y0 + 1.0f,   x1 = x0 + 1.0f;
        float vy0 = (y0 >= 0.f && y0 <= 63.f) ? 1.f : 0.f;
        float vy1 = (y1 >= 0.f && y1 <= 63.f) ? 1.f : 0.f;
        float vx0 = (x0 >= 0.f && x0 <= 63.f) ? 1.f : 0.f;
        float vx1 = (x1 >= 0.f && x1 <= 63.f) ? 1.f : 0.f;
        int iy0 = (int)fminf(fmaxf(y0, 0.f), 63.f);
        int iy1 = (int)fminf(fmaxf(y1, 0.f), 63.f);
        int ix0 = (int)fminf(fmaxf(x0, 0.f), 63.f);
        int ix1 = (int)fminf(fmaxf(x1, 0.f), 63.f);
        swp[t] = make_float4(hh*hw*m*vy0*vx0, hh*lw*m*vy0*vx1,
                             lh*hw*m*vy1*vx0, lh*lw*m*vy1*vx1);
        uint2 ip;
        ip.x = (uint32_t)(iy0*64 + ix0) | ((uint32_t)(iy0*64 + ix1) << 16);
        ip.y = (uint32_t)(iy1*64 + ix0) | ((uint32_t)(iy1*64 + ix1) << 16);
        sip[t] = ip;
    }
    __syncthreads();

    float acc[2][8][4];
    #pragma unroll
    for (int i = 0; i < 2; i++)
        #pragma unroll
        for (int j = 0; j < 8; j++)
            #pragma unroll
            for (int q = 0; q < 4; q++) acc[i][j][q] = 0.f;

    const float* xbase = x + ((size_t)nIdx * C_IN << 12);

    // B stage loader (1024 x 16B ops, 2 per thread)
    auto load_B = [&](int st, int ch) {
        const int k0 = ch * BK;
        const uint32_t bb = sb + B_OFF + st * B_SZ;
        #pragma unroll
        for (int it = 0; it < 2; it++) {
            int idx = tid + it * 512;
            int row = idx >> 2, q = idx & 3;
            cp16(bb + row * BPITCH + q * 16,
                 g_wtF + (size_t)row * KDIM + k0 + q * 8);
        }
        asm volatile("cp.async.commit_group;\n" ::: "memory");
    };

    // gather half h (pxblks h*2, h*2+1) of chunk ch into registers
    float g[2][2][4];
    auto gather_half = [&](int ch, int h) {
        const int k = ch >> 3;
        const int c0 = (ch & 7) * 32 + wid * 2;
        const float* xb0 = xbase + ((size_t)c0 << 12);
        const float* xb1 = xb0 + HW;
        #pragma unroll
        for (int pb = 0; pb < 2; pb++) {
            int p = (h * 2 + pb) * 32 + lid;
            uint2 ip = sip[k * 128 + p];
            int i0 = ip.x & 0xffff, i1 = ip.x >> 16;
            int i2 = ip.y & 0xffff, i3 = ip.y >> 16;
            g[pb][0][0] = xb0[i0]; g[pb][0][1] = xb0[i1];
            g[pb][0][2] = xb0[i2]; g[pb][0][3] = xb0[i3];
            g[pb][1][0] = xb1[i0]; g[pb][1][1] = xb1[i1];
            g[pb][1][2] = xb1[i2]; g[pb][1][3] = xb1[i3];
        }
    };
    // lerp + store half h of chunk ch into A buffer st
    auto lerp_sts = [&](int ch, int h, int st) {
        const int k = ch >> 3;
        const uint32_t ab = sb + A_OFF + st * A_SZ;
        #pragma unroll
        for (int pb = 0; pb < 2; pb++) {
            int p = (h * 2 + pb) * 32 + lid;
            float4 w = swp[k * 128 + p];
            #pragma unroll
            for (int cc = 0; cc < 2; cc++) {
                float v = w.x * g[pb][cc][0] + w.y * g[pb][cc][1]
                        + w.z * g[pb][cc][2] + w.w * g[pb][cc][3];
                sts16(ab + (wid * 2 + cc) * APITCH + (uint32_t)p * 2,
                      __half_as_ushort(__float2half_rn(v)));
            }
        }
    };

    // ldmatrix per-thread address components
    const int qq = lid >> 3;
    const int jr = lid & 7;
    const uint32_t aoff = (uint32_t)(((qq >> 1) * 8 + jr) * APITCH
                                     + (warpM * 32 + (qq & 1) * 8) * 2);
    const uint32_t boff = (uint32_t)((warpN * 64 + (qq >> 1) * 8 + jr) * BPITCH
                                     + (qq & 1) * 16);

    // ---- initial stage 0 ----
    load_B(0, 0);
    gather_half(0, 0); lerp_sts(0, 0, 0);
    gather_half(0, 1); lerp_sts(0, 1, 0);
    asm volatile("cp.async.wait_group 0;\n" ::: "memory");
    __syncthreads();

    for (int ch = 0; ch < NITER; ch++) {
        const int st = ch & 1;
        const int nst = st ^ 1;
        const bool more = (ch + 1 < NITER);
        if (more) load_B(nst, ch + 1);

        const uint32_t ab = sb + A_OFF + st * A_SZ;
        const uint32_t bb = sb + B_OFF + st * B_SZ;

        // half 0 gathers for next chunk (latency hidden behind kp=0 MMAs)
        if (more) gather_half(ch + 1, 0);
        {
            uint32_t Af[2][4], Bf[4][4];
            #pragma unroll
            for (int mi = 0; mi < 2; mi++)
                ldmx4t(Af[mi], ab + aoff + mi * 32);
            #pragma unroll
            for (int pi = 0; pi < 4; pi++)
                ldmx4(Bf[pi], bb + boff + pi * (16 * BPITCH));
            #pragma unroll
            for (int mi = 0; mi < 2; mi++)
                #pragma unroll
                for (int pi = 0; pi < 4; pi++) {
                    mma_f16(acc[mi][pi*2],   Af[mi], &Bf[pi][0]);
                    mma_f16(acc[mi][pi*2+1], Af[mi], &Bf[pi][2]);
                }
        }
        if (more) { lerp_sts(ch + 1, 0, nst); gather_half(ch + 1, 1); }
        {
            uint32_t Af[2][4], Bf[4][4];
            #pragma unroll
            for (int mi = 0; mi < 2; mi++)
                ldmx4t(Af[mi], ab + aoff + 16 * APITCH + mi * 32);
            #pragma unroll
            for (int pi = 0; pi < 4; pi++)
                ldmx4(Bf[pi], bb + boff + pi * (16 * BPITCH) + 32);
            #pragma unroll
            for (int mi = 0; mi < 2; mi++)
                #pragma unroll
                for (int pi = 0; pi < 4; pi++) {
                    mma_f16(acc[mi][pi*2],   Af[mi], &Bf[pi][0]);
                    mma_f16(acc[mi][pi*2+1], Af[mi], &Bf[pi][2]);
                }
        }
        if (more) lerp_sts(ch + 1, 1, nst);

        asm volatile("cp.async.wait_group 0;\n" ::: "memory");
        __syncthreads();
    }

    // ---- epilogue: direct coalesced-ish stores ----
    #pragma unroll
    for (int mi = 0; mi < 2; mi++) {
        int r = hwb + warpM * 32 + mi * 16 + (lid >> 2);
        #pragma unroll
        for (int jj = 0; jj < 8; jj++) {
            int oc = warpN * 64 + jj * 8 + (lid & 3) * 2;
            size_t base = ((size_t)(nIdx * OC + oc) << 12);
            out[base + r]            = acc[mi][jj][0];
            out[base + 4096 + r]     = acc[mi][jj][1];
            out[base + r + 8]        = acc[mi][jj][2];
            out[base + 4096 + r + 8] = acc[mi][jj][3];
        }
    }
}

// ---------------------------------------------------------------------------
extern "C" void kernel_launch(void* const* d_in, const int* in_sizes, int n_in,
                              void* d_out, int out_size)
{
    const float* x  = (const float*)d_in[0];
    const float* ow = (const float*)d_in[1];
    const float* ob = (const float*)d_in[2];
    const float* dw = (const float*)d_in[3];
    float* out = (float*)d_out;

    cudaFuncSetAttribute(offset_conv_kernel,
        cudaFuncAttributeMaxDynamicSharedMemorySize, 64*324*4 + 4*27*64*4);
    cudaFuncSetAttribute(fused_gemm_kernel,
        cudaFuncAttributeMaxDynamicSharedMemorySize, FUSED_SMEM);

    offset_conv_kernel<<<dim3(H_IM, N_B, 4), 256, 64*324*4 + 4*27*64*4>>>(x, ow);
    reduce_om_kernel<<<(N_B*OMC*HW)/256, 256>>>(ob);
    reorder_w_kernel<<<OC, C_IN>>>(dw);
    fused_gemm_kernel<<<NPIX/128, 512, FUSED_SMEM>>>(x, out);
}